// round 1
// baseline (speedup 1.0000x reference)
#include <cuda_runtime.h>
#include <math.h>

// ---------------------------------------------------------------------------
// NeRF MLP, fully fused, fp32 SIMT baseline.
// Each CTA (256 threads) processes 64 samples; all activations stay in SMEM
// (feature-major: act[f][r], row-stride 64). Weights streamed per-layer into
// a transposed SMEM tile wt[k][c]. Thread tile = 4 rows x CT cols in regs.
// ---------------------------------------------------------------------------

#define ROWS     64
#define RS       64            // row stride (floats) of feature-major buffers
#define NTHREADS 256
#define WT_K     32            // k-chunk
#define WT_STR   260           // padded col stride of weight tile (mult of 4, %32==4)

#define A_ROWS   320           // holds h(256) + pe_x(63) for the skip concat
#define B_ROWS   288           // holds hc(256) + pe_d(27)
#define B_OFF    (A_ROWS * RS)
#define WT_OFF   (B_OFF + B_ROWS * RS)
#define PED_OFF  (WT_OFF + WT_K * WT_STR)
#define SMEM_FLOATS (PED_OFF + 27 * RS)
#define SMEM_BYTES  (SMEM_FLOATS * 4)   // 195840 B < 227KB limit

// out = relu(in @ W^T + b); in: K features x 64 rows (SMEM), W: [N,K] row-major (GMEM)
template<int CT>
__device__ __forceinline__ void gemm_relu(
    const float* __restrict__ W, const float* __restrict__ bias,
    const float* __restrict__ inS, float* __restrict__ outS,
    float* __restrict__ wt, int K, int tid)
{
    constexpr int N = CT * 16;
    const int tr = tid & 15;       // row group (4 rows each)
    const int tc = tid >> 4;       // col group (CT cols each)
    const int r0 = tr * 4;
    const int c0 = tc * CT;

    float acc[4][CT];
#pragma unroll
    for (int i = 0; i < 4; i++)
#pragma unroll
        for (int j = 0; j < CT; j++) acc[i][j] = 0.f;

    for (int kk = 0; kk < K; kk += WT_K) {
        const int kc = min(WT_K, K - kk);
        __syncthreads();   // previous tile fully consumed / prev epilogue visible
        // stage W tile transposed: wt[k][c] = W[c*K + kk + k]  (coalesced: k fastest)
#pragma unroll 8
        for (int idx = tid; idx < WT_K * N; idx += NTHREADS) {
            const int k = idx & (WT_K - 1);
            const int c = idx >> 5;
            if (k < kc) wt[k * WT_STR + c] = __ldg(&W[c * K + kk + k]);
        }
        __syncthreads();

        if (kc == WT_K) {
#pragma unroll 4
            for (int k = 0; k < WT_K; k++) {
                float av[4];
                *(float4*)av = *(const float4*)&inS[(kk + k) * RS + r0];
                float wv[CT];
#pragma unroll
                for (int q = 0; q < CT / 4; q++)
                    *(float4*)&wv[4 * q] = *(const float4*)&wt[k * WT_STR + c0 + 4 * q];
#pragma unroll
                for (int i = 0; i < 4; i++)
#pragma unroll
                    for (int j = 0; j < CT; j++)
                        acc[i][j] = fmaf(av[i], wv[j], acc[i][j]);
            }
        } else {
            for (int k = 0; k < kc; k++) {
                float av[4];
                *(float4*)av = *(const float4*)&inS[(kk + k) * RS + r0];
                float wv[CT];
#pragma unroll
                for (int q = 0; q < CT / 4; q++)
                    *(float4*)&wv[4 * q] = *(const float4*)&wt[k * WT_STR + c0 + 4 * q];
#pragma unroll
                for (int i = 0; i < 4; i++)
#pragma unroll
                    for (int j = 0; j < CT; j++)
                        acc[i][j] = fmaf(av[i], wv[j], acc[i][j]);
            }
        }
    }
    __syncthreads();

    // epilogue: bias + relu, write feature-major
#pragma unroll
    for (int j = 0; j < CT; j++) {
        const int c = c0 + j;
        const float bv = __ldg(&bias[c]);
        float4 v;
        v.x = fmaxf(acc[0][j] + bv, 0.f);
        v.y = fmaxf(acc[1][j] + bv, 0.f);
        v.z = fmaxf(acc[2][j] + bv, 0.f);
        v.w = fmaxf(acc[3][j] + bv, 0.f);
        *(float4*)&outS[c * RS + r0] = v;
    }
    __syncthreads();
}

__global__ void __launch_bounds__(NTHREADS, 1)
nerf_mlp_kernel(
    const float* __restrict__ xw, const float* __restrict__ dd,
    const float* __restrict__ W1, const float* __restrict__ b1,
    const float* __restrict__ W2, const float* __restrict__ b2,
    const float* __restrict__ W3, const float* __restrict__ b3,
    const float* __restrict__ W4, const float* __restrict__ b4,
    const float* __restrict__ W5, const float* __restrict__ b5,
    const float* __restrict__ W6, const float* __restrict__ b6,
    const float* __restrict__ W7, const float* __restrict__ b7,
    const float* __restrict__ W8, const float* __restrict__ b8,
    const float* __restrict__ Ws, const float* __restrict__ bs,
    const float* __restrict__ Wc, const float* __restrict__ bc,
    const float* __restrict__ Wd, const float* __restrict__ bd,
    const float* __restrict__ Wo, const float* __restrict__ bo,
    float* __restrict__ out, int Btot)
{
    extern __shared__ float sm[];
    float* Ab = sm;                 // 320 x 64
    float* Bb = sm + B_OFF;         // 288 x 64
    float* wt = sm + WT_OFF;        // 32 x 260
    float* PD = sm + PED_OFF;       // 27 x 64

    const int tid  = threadIdx.x;
    const int base = blockIdx.x * ROWS;

    // --- positional encodings (one thread per row) ---
    if (tid < ROWS) {
        const int r = tid;
        const int g = base + r;
        if (g < Btot) {
            const float x = xw[3 * g], y = xw[3 * g + 1], z = xw[3 * g + 2];
            Ab[0 * RS + r] = x; Ab[1 * RS + r] = y; Ab[2 * RS + r] = z;
            Ab[(256 + 0) * RS + r] = x; Ab[(256 + 1) * RS + r] = y; Ab[(256 + 2) * RS + r] = z;
            float fr = 1.f;
#pragma unroll
            for (int i = 0; i < 10; i++) {
                float sx, cx, sy, cy, sz, cz;
                sincosf(x * fr, &sx, &cx);
                sincosf(y * fr, &sy, &cy);
                sincosf(z * fr, &sz, &cz);
                const int o = 3 + 6 * i;
                Ab[(o + 0) * RS + r] = sx; Ab[(o + 1) * RS + r] = sy; Ab[(o + 2) * RS + r] = sz;
                Ab[(o + 3) * RS + r] = cx; Ab[(o + 4) * RS + r] = cy; Ab[(o + 5) * RS + r] = cz;
                Ab[(256 + o + 0) * RS + r] = sx; Ab[(256 + o + 1) * RS + r] = sy; Ab[(256 + o + 2) * RS + r] = sz;
                Ab[(256 + o + 3) * RS + r] = cx; Ab[(256 + o + 4) * RS + r] = cy; Ab[(256 + o + 5) * RS + r] = cz;
                fr *= 2.f;
            }
            float dx = dd[3 * g], dy = dd[3 * g + 1], dz = dd[3 * g + 2];
            const float inv = 1.f / (sqrtf(dx * dx + dy * dy + dz * dz) + 1e-8f);
            dx *= inv; dy *= inv; dz *= inv;
            PD[0 * RS + r] = dx; PD[1 * RS + r] = dy; PD[2 * RS + r] = dz;
            fr = 1.f;
#pragma unroll
            for (int i = 0; i < 4; i++) {
                float sx, cx, sy, cy, sz, cz;
                sincosf(dx * fr, &sx, &cx);
                sincosf(dy * fr, &sy, &cy);
                sincosf(dz * fr, &sz, &cz);
                const int o = 3 + 6 * i;
                PD[(o + 0) * RS + r] = sx; PD[(o + 1) * RS + r] = sy; PD[(o + 2) * RS + r] = sz;
                PD[(o + 3) * RS + r] = cx; PD[(o + 4) * RS + r] = cy; PD[(o + 5) * RS + r] = cz;
                fr *= 2.f;
            }
        }
    }
    __syncthreads();

    // --- trunk ---
    gemm_relu<16>(W1, b1, Ab, Bb, wt,  63, tid);
    gemm_relu<16>(W2, b2, Bb, Ab, wt, 256, tid);
    gemm_relu<16>(W3, b3, Ab, Bb, wt, 256, tid);
    gemm_relu<16>(W4, b4, Bb, Ab, wt, 256, tid);
    // Ab rows 0..255 = h4, rows 256..318 = pe_x (never touched by epilogues)
    gemm_relu<16>(W5, b5, Ab, Bb, wt, 319, tid);
    gemm_relu<16>(W6, b6, Bb, Ab, wt, 256, tid);
    gemm_relu<16>(W7, b7, Ab, Bb, wt, 256, tid);
    gemm_relu<16>(W8, b8, Bb, Ab, wt, 256, tid);
    // h8 in Ab[0..255]

    // --- sigma head: relu(h8 @ Ws^T + bs) ---
    if (tid < ROWS && base + tid < Btot) {
        const int r = tid;
        float acc = __ldg(&bs[0]);
#pragma unroll 8
        for (int k = 0; k < 256; k++)
            acc = fmaf(__ldg(&Ws[k]), Ab[k * RS + r], acc);
        out[(size_t)3 * Btot + base + r] = fmaxf(acc, 0.f);
    }

    // --- color branch ---
    gemm_relu<16>(Wc, bc, Ab, Bb, wt, 256, tid);
    // append pe_d: Bb rows 256..282
    if (tid < ROWS) {
#pragma unroll
        for (int f = 0; f < 27; f++)
            Bb[(256 + f) * RS + tid] = PD[f * RS + tid];
    }
    __syncthreads();
    gemm_relu<8>(Wd, bd, Bb, Ab, wt, 283, tid);   // 283 -> 128, in Ab[0..127]

    // --- rgb head: sigmoid(hcd @ Wo^T + bo) ---
    if (tid < ROWS && base + tid < Btot) {
        const int r = tid;
        const int g = base + r;
#pragma unroll
        for (int c = 0; c < 3; c++) {
            float acc = __ldg(&bo[c]);
#pragma unroll 8
            for (int k = 0; k < 128; k++)
                acc = fmaf(__ldg(&Wo[c * 128 + k]), Ab[k * RS + r], acc);
            out[(size_t)3 * g + c] = 1.f / (1.f + expf(-acc));
        }
    }
}

extern "C" void kernel_launch(void* const* d_in, const int* in_sizes, int n_in,
                              void* d_out, int out_size)
{
    const float* xw = (const float*)d_in[0];
    const float* dd = (const float*)d_in[1];
    const int Btot = in_sizes[0] / 3;
    const int blocks = (Btot + ROWS - 1) / ROWS;

    cudaFuncSetAttribute(nerf_mlp_kernel,
                         cudaFuncAttributeMaxDynamicSharedMemorySize, SMEM_BYTES);

    nerf_mlp_kernel<<<blocks, NTHREADS, SMEM_BYTES>>>(
        xw, dd,
        (const float*)d_in[2],  (const float*)d_in[3],
        (const float*)d_in[4],  (const float*)d_in[5],
        (const float*)d_in[6],  (const float*)d_in[7],
        (const float*)d_in[8],  (const float*)d_in[9],
        (const float*)d_in[10], (const float*)d_in[11],
        (const float*)d_in[12], (const float*)d_in[13],
        (const float*)d_in[14], (const float*)d_in[15],
        (const float*)d_in[16], (const float*)d_in[17],
        (const float*)d_in[18], (const float*)d_in[19],
        (const float*)d_in[20], (const float*)d_in[21],
        (const float*)d_in[22], (const float*)d_in[23],
        (const float*)d_in[24], (const float*)d_in[25],
        (float*)d_out, Btot);
}